// round 3
// baseline (speedup 1.0000x reference)
#include <cuda_runtime.h>
#include <math.h>

#define Bb   128
#define Ss   256
#define Ed   300
#define Hd   1024
#define NCc  3
#define Rr   256                 // 2*Bb rows (premise rows 0..127, hypothesis 128..255)
#define NROWS (2*Bb*Ss)          // 65536 flattened (which, b, s) rows

// ---------------- device scratch (static, allocation-free) ----------------
__device__ float g_x   [(size_t)NROWS * Ed];   // projected embeddings
__device__ float g_xn2 [NROWS];                // ||x||^2 post-project
__device__ float g_ux  [(size_t)NROWS * Hd];   // mmatvec(x_t, U) results
__device__ float g_h   [Rr * Hd];              // current hidden states (both RNNs)
__device__ float g_hn2 [Rr];                   // ||h||^2
__device__ float g_upart[4 * Rr * Hd];         // k-split GEMM partials
__device__ float g_last[Rr * Hd];              // h at t = len-1
__device__ float g_lastn2[Rr];
__device__ float g_rep [Rr * Hd];              // hlinear outputs

// ---------------- helpers ----------------
__device__ __forceinline__ float warpSum(float v) {
    #pragma unroll
    for (int o = 16; o; o >>= 1) v += __shfl_xor_sync(0xffffffffu, v, o);
    return v;
}

// block = 256 threads (8 warps). Reduces NV values; result broadcast to all threads.
template<int NV>
__device__ __forceinline__ void blockReduceN(float (&vals)[NV], float (*sred)[8]) {
    int tid = threadIdx.x, lane = tid & 31, w = tid >> 5;
    #pragma unroll
    for (int i = 0; i < NV; i++) {
        float v = warpSum(vals[i]);
        if (lane == 0) sred[i][w] = v;
    }
    __syncthreads();
    #pragma unroll
    for (int i = 0; i < NV; i++) {
        float t = 0.f;
        #pragma unroll
        for (int k = 0; k < 8; k++) t += sred[i][k];
        vals[i] = t;
    }
    __syncthreads();
}

__device__ __forceinline__ float artanh_c(float x) {
    // matches _artanh: clip to 1-1e-5 (inputs are >= 0 here)
    return atanhf(fminf(x, 0.99999f));
}

// ---------------- init ----------------
__global__ void k_init() {
    int i = blockIdx.x * blockDim.x + threadIdx.x;
    int n = Rr * Hd;
    for (; i < n; i += gridDim.x * blockDim.x) g_h[i] = 0.f;
    if (blockIdx.x == 0 && threadIdx.x < Rr) g_hn2[threadIdx.x] = 0.f;
}

// ---------------- embedding + project (warp per row) ----------------
__global__ void k_embed(const int* __restrict__ prem, const int* __restrict__ hyp,
                        const float* __restrict__ emb) {
    int warp = (blockIdx.x * blockDim.x + threadIdx.x) >> 5;
    int lane = threadIdx.x & 31;
    if (warp >= NROWS) return;
    int which = warp / (Bb * Ss);
    int idx   = warp % (Bb * Ss);
    int b = idx / Ss, s = idx % Ss;
    int tok = which ? hyp[b * Ss + s] : prem[b * Ss + s];
    const float* src = emb + (size_t)tok * Ed;
    float s2 = 0.f;
    for (int e = lane; e < Ed; e += 32) { float v = src[e]; s2 += v * v; }
    s2 = warpSum(s2);
    float n  = sqrtf(fmaxf(s2, 1e-12f));
    float sc = fminf(1.0f, 0.999f / n);
    float* dst = g_x + (size_t)warp * Ed;
    for (int e = lane; e < Ed; e += 32) dst[e] = src[e] * sc;
    if (lane == 0) g_xn2[warp] = s2 * sc * sc;
}

// ---------------- GEMM: g_ux = g_x @ U (128x128x8 tiles, TM=TN=8) ----------------
__global__ void k_gemm_ux(const float* __restrict__ Up, const float* __restrict__ Uh) {
    __shared__ float As[8][132];
    __shared__ float Bs[8][132];
    int row0 = blockIdx.x * 128, col0 = blockIdx.y * 128;
    int which = row0 / (Bb * Ss);
    const float* Bm = which ? Uh : Up;
    int tid = threadIdx.x;
    int tx = tid & 15, ty = tid >> 4;
    float acc[8][8];
    #pragma unroll
    for (int i = 0; i < 8; i++)
        #pragma unroll
        for (int j = 0; j < 8; j++) acc[i][j] = 0.f;

    int ar = tid >> 1, ak = (tid & 1) * 4;
    int bk = tid >> 5, bc = (tid & 31) * 4;

    for (int k0 = 0; k0 < Ed; k0 += 8) {
        float4 av = make_float4(0.f, 0.f, 0.f, 0.f);
        if (k0 + ak < Ed)
            av = *(const float4*)(g_x + (size_t)(row0 + ar) * Ed + k0 + ak);
        As[ak + 0][ar] = av.x; As[ak + 1][ar] = av.y;
        As[ak + 2][ar] = av.z; As[ak + 3][ar] = av.w;
        float4 bv = make_float4(0.f, 0.f, 0.f, 0.f);
        if (k0 + bk < Ed)
            bv = *(const float4*)(Bm + (size_t)(k0 + bk) * Hd + col0 + bc);
        *(float4*)&Bs[bk][bc] = bv;
        __syncthreads();
        #pragma unroll
        for (int kk = 0; kk < 8; kk++) {
            float a[8], bb[8];
            *(float4*)(a)     = *(const float4*)&As[kk][ty * 8];
            *(float4*)(a + 4) = *(const float4*)&As[kk][ty * 8 + 4];
            *(float4*)(bb)     = *(const float4*)&Bs[kk][tx * 8];
            *(float4*)(bb + 4) = *(const float4*)&Bs[kk][tx * 8 + 4];
            #pragma unroll
            for (int i = 0; i < 8; i++)
                #pragma unroll
                for (int j = 0; j < 8; j++) acc[i][j] += a[i] * bb[j];
        }
        __syncthreads();
    }
    #pragma unroll
    for (int i = 0; i < 8; i++) {
        float* dst = g_ux + (size_t)(row0 + ty * 8 + i) * Hd + col0 + tx * 8;
        *(float4*)dst       = *(float4*)&acc[i][0];
        *(float4*)(dst + 4) = *(float4*)&acc[i][4];
    }
}

// ---------------- mmatvec nonlinearity + project on g_ux (warp per row) ----------------
__global__ void k_ux_post() {
    int row  = (blockIdx.x * blockDim.x + threadIdx.x) >> 5;
    int lane = threadIdx.x & 31;
    if (row >= NROWS) return;
    float* u = g_ux + (size_t)row * Hd;
    float v[32];
    float s2 = 0.f;
    #pragma unroll
    for (int i = 0; i < 32; i++) { v[i] = u[i * 32 + lane]; s2 += v[i] * v[i]; }
    float un2 = warpSum(s2);
    float xn = sqrtf(fmaxf(g_xn2[row], 1e-12f));
    float un = sqrtf(fmaxf(un2, 1e-12f));
    float mm = tanhf(un / xn * artanh_c(xn)) / un;
    float vn2 = mm * mm * un2;
    float pn  = sqrtf(fmaxf(vn2, 1e-12f));
    float ps  = fminf(1.0f, 0.999f / pn);
    float c   = mm * ps;
    #pragma unroll
    for (int i = 0; i < 32; i++) u[i * 32 + lane] = v[i] * c;
}

// ---------------- recurrent GEMM: u_part[ks] = h @ W (64x64 tiles, k-split 4) ----------------
__global__ void k_gemm_step(int useLast, const float* __restrict__ W0,
                            const float* __restrict__ W1) {
    __shared__ float As[16][68];
    __shared__ float Bs[16][68];
    const float* Asrc = useLast ? g_last : g_h;
    int row0 = blockIdx.x * 64, col0 = blockIdx.y * 64, kbase = blockIdx.z * 256;
    const float* Wm = (row0 < Bb) ? W0 : W1;
    int tid = threadIdx.x;
    int tx = tid & 15, ty = tid >> 4;
    float acc[4][4];
    #pragma unroll
    for (int i = 0; i < 4; i++)
        #pragma unroll
        for (int j = 0; j < 4; j++) acc[i][j] = 0.f;

    int ar = tid >> 2, ak = (tid & 3) * 4;
    int bk = tid >> 4, bc = (tid & 15) * 4;

    for (int k0 = kbase; k0 < kbase + 256; k0 += 16) {
        float4 av = *(const float4*)(Asrc + (size_t)(row0 + ar) * Hd + k0 + ak);
        As[ak + 0][ar] = av.x; As[ak + 1][ar] = av.y;
        As[ak + 2][ar] = av.z; As[ak + 3][ar] = av.w;
        float4 bv = *(const float4*)(Wm + (size_t)(k0 + bk) * Hd + col0 + bc);
        *(float4*)&Bs[bk][bc] = bv;
        __syncthreads();
        #pragma unroll
        for (int kk = 0; kk < 16; kk++) {
            float a[4], bb[4];
            *(float4*)a  = *(const float4*)&As[kk][ty * 4];
            *(float4*)bb = *(const float4*)&Bs[kk][tx * 4];
            #pragma unroll
            for (int i = 0; i < 4; i++)
                #pragma unroll
                for (int j = 0; j < 4; j++) acc[i][j] += a[i] * bb[j];
        }
        __syncthreads();
    }
    float* base = g_upart + (size_t)blockIdx.z * Rr * Hd;
    #pragma unroll
    for (int i = 0; i < 4; i++)
        *(float4*)(base + (size_t)(row0 + ty * 4 + i) * Hd + col0 + tx * 4) =
            *(float4*)&acc[i][0];
}

// ---------------- per-step Mobius epilogue (CTA per row) ----------------
__global__ void k_step_post(int ts, const int* __restrict__ p_len,
                            const int* __restrict__ h_len,
                            const float* __restrict__ bp,
                            const float* __restrict__ bh) {
    __shared__ float sred[8][8];
    int r = blockIdx.x, tid = threadIdx.x;
    int which = r >> 7, b = r & 127;
    const float* bias = which ? bh : bp;
    int j0 = tid * 4;

    // sum k-split partials
    float u[4];
    {
        float4 a0 = *(const float4*)&g_upart[0 * Rr * Hd + (size_t)r * Hd + j0];
        float4 a1 = *(const float4*)&g_upart[1 * Rr * Hd + (size_t)r * Hd + j0];
        float4 a2 = *(const float4*)&g_upart[2 * Rr * Hd + (size_t)r * Hd + j0];
        float4 a3 = *(const float4*)&g_upart[3 * Rr * Hd + (size_t)r * Hd + j0];
        u[0] = a0.x + a1.x + a2.x + a3.x;
        u[1] = a0.y + a1.y + a2.y + a3.y;
        u[2] = a0.z + a1.z + a2.z + a3.z;
        u[3] = a0.w + a1.w + a2.w + a3.w;
    }
    float ux[4], bv[4];
    {
        float4 t4 = *(const float4*)&g_ux[((size_t)which * Bb * Ss + (size_t)b * Ss + ts) * Hd + j0];
        ux[0] = t4.x; ux[1] = t4.y; ux[2] = t4.z; ux[3] = t4.w;
        float4 b4 = *(const float4*)&bias[j0];
        bv[0] = b4.x; bv[1] = b4.y; bv[2] = b4.z; bv[3] = b4.w;
    }

    float red[6] = {0.f, 0.f, 0.f, 0.f, 0.f, 0.f};
    #pragma unroll
    for (int i = 0; i < 4; i++) {
        red[0] += u[i]  * u[i];
        red[1] += ux[i] * ux[i];
        red[2] += bv[i] * bv[i];
        red[3] += u[i]  * ux[i];
        red[4] += u[i]  * bv[i];
        red[5] += ux[i] * bv[i];
    }
    blockReduceN<6>(red, sred);
    float su2 = red[0], sux2 = red[1], sb2 = red[2];
    float suux = red[3], sub = red[4], suxb = red[5];

    // mmatvec(h, W) scale + project  -> v = c1 * u
    float xn = sqrtf(fmaxf(g_hn2[r], 1e-12f));
    float un = sqrtf(fmaxf(su2, 1e-12f));
    float mm = tanhf(un / xn * artanh_c(xn)) / un;
    float vn2 = mm * mm * su2;
    float pn = sqrtf(fmaxf(vn2, 1e-12f));
    float ps = fminf(1.0f, 0.999f / pn);
    float c1 = mm * ps;

    // madd(v, ux) + project -> z = A1*u + B1*ux
    float x2 = c1 * c1 * su2, y2 = sux2, xy = c1 * suux;
    float al = 1.f + 2.f * xy + y2;
    float be = 1.f - x2;
    float den = fmaxf(1.f + 2.f * xy + x2 * y2, 1e-12f);
    float zn2p = (al * al * x2 + 2.f * al * be * xy + be * be * y2) / (den * den);
    float zn = sqrtf(fmaxf(zn2p, 1e-12f));
    float zs = fminf(1.0f, 0.999f / zn);
    float c2 = zs / den;
    float A1 = c2 * al * c1, B1 = c2 * be;
    float z2 = zn2p * zs * zs;

    // madd(z, bias) + project -> w = Au*u + Aux*ux + Ab*b
    float xy2 = A1 * sub + B1 * suxb;
    float al2 = 1.f + 2.f * xy2 + sb2;
    float be2 = 1.f - z2;
    float den2 = fmaxf(1.f + 2.f * xy2 + z2 * sb2, 1e-12f);
    float wn2p = (al2 * al2 * z2 + 2.f * al2 * be2 * xy2 + be2 * be2 * sb2) / (den2 * den2);
    float wn = sqrtf(fmaxf(wn2p, 1e-12f));
    float ws = fminf(1.0f, 0.999f / wn);
    float c3 = ws / den2;
    float Au = c3 * al2 * A1, Aux = c3 * al2 * B1, Ab = c3 * be2;
    float wnf2 = wn2p * ws * ws;
    float wnf = sqrtf(fmaxf(wnf2, 1e-12f));

    // mtanh: log0 scale, elementwise tanh, reduce, exp0 + project
    float lam = artanh_c(wnf) / wnf;
    float tt[4];
    float red2[1] = {0.f};
    #pragma unroll
    for (int i = 0; i < 4; i++) {
        tt[i] = tanhf(lam * (Au * u[i] + Aux * ux[i] + Ab * bv[i]));
        red2[0] += tt[i] * tt[i];
    }
    blockReduceN<1>(red2, sred);
    float st2 = red2[0];
    float tn = sqrtf(fmaxf(st2, 1e-12f));
    float es = tanhf(tn) / tn;
    float en2 = es * es * st2;
    float enn = sqrtf(fmaxf(en2, 1e-12f));
    float epss = fminf(1.0f, 0.999f / enn);
    float c4 = es * epss;

    float4 hv;
    hv.x = c4 * tt[0]; hv.y = c4 * tt[1]; hv.z = c4 * tt[2]; hv.w = c4 * tt[3];
    *(float4*)&g_h[(size_t)r * Hd + j0] = hv;
    int lenv = which ? h_len[b] : p_len[b];
    bool save = (ts == lenv - 1);
    if (save) *(float4*)&g_last[(size_t)r * Hd + j0] = hv;
    if (tid == 0) {
        float hn2n = c4 * c4 * st2;
        g_hn2[r] = hn2n;
        if (save) g_lastn2[r] = hn2n;
    }
}

// ---------------- hlinear epilogue: g_rep = madd(mmatvec(last, Wc), bc) ----------------
__global__ void k_final_post(const float* __restrict__ bcp, const float* __restrict__ bch) {
    __shared__ float sred[8][8];
    int r = blockIdx.x, tid = threadIdx.x;
    int which = r >> 7;
    const float* bias = which ? bch : bcp;
    int j0 = tid * 4;

    float u[4];
    {
        float4 a0 = *(const float4*)&g_upart[0 * Rr * Hd + (size_t)r * Hd + j0];
        float4 a1 = *(const float4*)&g_upart[1 * Rr * Hd + (size_t)r * Hd + j0];
        float4 a2 = *(const float4*)&g_upart[2 * Rr * Hd + (size_t)r * Hd + j0];
        float4 a3 = *(const float4*)&g_upart[3 * Rr * Hd + (size_t)r * Hd + j0];
        u[0] = a0.x + a1.x + a2.x + a3.x;
        u[1] = a0.y + a1.y + a2.y + a3.y;
        u[2] = a0.z + a1.z + a2.z + a3.z;
        u[3] = a0.w + a1.w + a2.w + a3.w;
    }
    float bv[4];
    {
        float4 b4 = *(const float4*)&bias[j0];
        bv[0] = b4.x; bv[1] = b4.y; bv[2] = b4.z; bv[3] = b4.w;
    }
    float red[3] = {0.f, 0.f, 0.f};
    #pragma unroll
    for (int i = 0; i < 4; i++) {
        red[0] += u[i] * u[i];
        red[1] += bv[i] * bv[i];
        red[2] += u[i] * bv[i];
    }
    blockReduceN<3>(red, sred);
    float su2 = red[0], sb2 = red[1], sub = red[2];

    float xn = sqrtf(fmaxf(g_lastn2[r], 1e-12f));
    float un = sqrtf(fmaxf(su2, 1e-12f));
    float mm = tanhf(un / xn * artanh_c(xn)) / un;
    float vn2 = mm * mm * su2;
    float pn = sqrtf(fmaxf(vn2, 1e-12f));
    float ps = fminf(1.0f, 0.999f / pn);
    float c1 = mm * ps;

    float x2 = c1 * c1 * su2, y2 = sb2, xy = c1 * sub;
    float al = 1.f + 2.f * xy + y2;
    float be = 1.f - x2;
    float den = fmaxf(1.f + 2.f * xy + x2 * y2, 1e-12f);
    float zn2p = (al * al * x2 + 2.f * al * be * xy + be * be * y2) / (den * den);
    float zn = sqrtf(fmaxf(zn2p, 1e-12f));
    float zs = fminf(1.0f, 0.999f / zn);
    float c2 = zs / den;
    float A1 = c2 * al * c1, B1 = c2 * be;

    float4 o;
    o.x = A1 * u[0] + B1 * bv[0];
    o.y = A1 * u[1] + B1 * bv[1];
    o.z = A1 * u[2] + B1 * bv[2];
    o.w = A1 * u[3] + B1 * bv[3];
    *(float4*)&g_rep[(size_t)r * Hd + j0] = o;
}

// ---------------- rep = madd(p_rep, h_rep); MLR logits ----------------
__global__ void k_mlr(const float* __restrict__ a_mlr, const float* __restrict__ p_mlr,
                      float* __restrict__ out) {
    __shared__ float sred[8][8];
    int b = blockIdx.x, tid = threadIdx.x;
    int j0 = tid * 4;
    float x[4], y[4];
    {
        float4 x4 = *(const float4*)&g_rep[(size_t)b * Hd + j0];
        float4 y4 = *(const float4*)&g_rep[(size_t)(128 + b) * Hd + j0];
        x[0] = x4.x; x[1] = x4.y; x[2] = x4.z; x[3] = x4.w;
        y[0] = y4.x; y[1] = y4.y; y[2] = y4.z; y[3] = y4.w;
    }
    float red[3] = {0.f, 0.f, 0.f};
    #pragma unroll
    for (int i = 0; i < 4; i++) {
        red[0] += x[i] * x[i];
        red[1] += y[i] * y[i];
        red[2] += x[i] * y[i];
    }
    blockReduceN<3>(red, sred);
    float x2 = red[0], y2 = red[1], xy = red[2];
    float al = 1.f + 2.f * xy + y2;
    float be = 1.f - x2;
    float den = fmaxf(1.f + 2.f * xy + x2 * y2, 1e-12f);
    float rn2 = (al * al * x2 + 2.f * al * be * xy + be * be * y2) / (den * den);
    float rn = sqrtf(fmaxf(rn2, 1e-12f));
    float rs = fminf(1.0f, 0.999f / rn);
    float cr = rs / den;
    float rep[4];
    #pragma unroll
    for (int i = 0; i < 4; i++) rep[i] = cr * (al * x[i] + be * y[i]);
    float rep2 = rn2 * rs * rs;

    for (int k = 0; k < NCc; k++) {
        float p[4], a[4];
        {
            float4 p4 = *(const float4*)&p_mlr[(size_t)k * Hd + j0];
            float4 a4 = *(const float4*)&a_mlr[(size_t)k * Hd + j0];
            p[0] = p4.x; p[1] = p4.y; p[2] = p4.z; p[3] = p4.w;
            a[0] = a4.x; a[1] = a4.y; a[2] = a4.z; a[3] = a4.w;
        }
        float r5[5] = {0.f, 0.f, 0.f, 0.f, 0.f};
        #pragma unroll
        for (int i = 0; i < 4; i++) {
            r5[0] += p[i] * p[i];        // sp2
            r5[1] += a[i] * a[i];        // sa2
            r5[2] += rep[i] * p[i];      // spr
            r5[3] += p[i] * a[i];        // spa
            r5[4] += rep[i] * a[i];      // sar
        }
        blockReduceN<5>(r5, sred);
        float sp2 = r5[0], sa2 = r5[1], spr = r5[2], spa = r5[3], sar = r5[4];

        // madd(-p, rep): x = -p, y = rep
        float xym = -spr;
        float alm = 1.f + 2.f * xym + rep2;
        float bem = 1.f - sp2;
        float denm = fmaxf(1.f + 2.f * xym + sp2 * rep2, 1e-12f);
        float zn2 = (alm * alm * sp2 + 2.f * alm * bem * xym + bem * bem * rep2) / (denm * denm);
        float znn = sqrtf(fmaxf(zn2, 1e-12f));
        float zss = fminf(1.0f, 0.999f / znn);
        float cz = zss / denm;
        float z2 = zn2 * zss * zss;
        float za = cz * (alm * (-spa) + bem * sar);
        float an = sqrtf(fmaxf(sa2, 1e-12f));
        float lamk = 2.0f / fmaxf(1.0f - sp2, 1e-5f);
        float logit = lamk * an * asinhf(2.0f * za / (fmaxf(1.0f - z2, 1e-5f) * an));
        if (tid == 0) out[b * NCc + k] = logit;
        __syncthreads();
    }
}

// ---------------- launch ----------------
extern "C" void kernel_launch(void* const* d_in, const int* in_sizes, int n_in,
                              void* d_out, int out_size) {
    const int*   prem   = (const int*)  d_in[0];
    const int*   p_len  = (const int*)  d_in[1];
    const int*   hyp    = (const int*)  d_in[2];
    const int*   h_len  = (const int*)  d_in[3];
    const float* emb    = (const float*)d_in[4];
    const float* Wp     = (const float*)d_in[5];
    const float* Up     = (const float*)d_in[6];
    const float* bp     = (const float*)d_in[7];
    const float* Wh     = (const float*)d_in[8];
    const float* Uh     = (const float*)d_in[9];
    const float* bh     = (const float*)d_in[10];
    const float* Wcp    = (const float*)d_in[11];
    const float* bcp    = (const float*)d_in[12];
    const float* Wch    = (const float*)d_in[13];
    const float* bch    = (const float*)d_in[14];
    const float* a_mlr  = (const float*)d_in[15];
    const float* p_mlr  = (const float*)d_in[16];
    float* out = (float*)d_out;

    k_init<<<128, 256>>>();
    k_embed<<<NROWS / 8, 256>>>(prem, hyp, emb);
    {
        dim3 g(NROWS / 128, Hd / 128);
        k_gemm_ux<<<g, 256>>>(Up, Uh);
    }
    k_ux_post<<<NROWS / 8, 256>>>();

    dim3 gstep(4, 16, 4);
    for (int t = 0; t < Ss; t++) {
        k_gemm_step<<<gstep, 256>>>(0, Wp, Wh);
        k_step_post<<<Rr, 256>>>(t, p_len, h_len, bp, bh);
    }
    k_gemm_step<<<gstep, 256>>>(1, Wcp, Wch);
    k_final_post<<<Rr, 256>>>(bcp, bch);
    k_mlr<<<Bb, 256>>>(a_mlr, p_mlr, out);
}

// round 4
// speedup vs baseline: 1.0352x; 1.0352x over previous
#include <cuda_runtime.h>
#include <math.h>

#define Bb   128
#define Ss   256
#define Ed   300
#define Hd   1024
#define NCc  3
#define Rr   256                 // 2*Bb rows (premise rows 0..127, hypothesis 128..255)
#define NROWS (2*Bb*Ss)          // 65536 flattened (which, b, s) rows

// ---------------- device scratch (static, allocation-free) ----------------
__device__ float g_x   [(size_t)NROWS * Ed];   // projected embeddings
__device__ float g_xn2 [NROWS];                // ||x||^2 post-project
__device__ float g_ux  [(size_t)NROWS * Hd];   // mmatvec(x_t, U) results
__device__ float g_h   [Rr * Hd];              // current hidden states (both RNNs)
__device__ float g_hn2 [Rr];                   // ||h||^2
__device__ float g_upart[4 * Rr * Hd];         // k-split GEMM partials
__device__ float g_last[Rr * Hd];              // h at t = len-1
__device__ float g_lastn2[Rr];
__device__ float g_rep [Rr * Hd];              // hlinear outputs

// ---------------- helpers ----------------
__device__ __forceinline__ float warpSum(float v) {
    #pragma unroll
    for (int o = 16; o; o >>= 1) v += __shfl_xor_sync(0xffffffffu, v, o);
    return v;
}

// block = 256 threads (8 warps). Reduces NV values; result broadcast to all threads.
template<int NV>
__device__ __forceinline__ void blockReduceN(float (&vals)[NV], float (*sred)[8]) {
    int tid = threadIdx.x, lane = tid & 31, w = tid >> 5;
    #pragma unroll
    for (int i = 0; i < NV; i++) {
        float v = warpSum(vals[i]);
        if (lane == 0) sred[i][w] = v;
    }
    __syncthreads();
    #pragma unroll
    for (int i = 0; i < NV; i++) {
        float t = 0.f;
        #pragma unroll
        for (int k = 0; k < 8; k++) t += sred[i][k];
        vals[i] = t;
    }
    __syncthreads();
}

__device__ __forceinline__ float artanh_c(float x) {
    // matches _artanh: clip to 1-1e-5 (inputs are >= 0 here)
    return atanhf(fminf(x, 0.99999f));
}

// ---------------- init ----------------
__global__ void k_init() {
    int i = blockIdx.x * blockDim.x + threadIdx.x;
    int n = Rr * Hd;
    for (; i < n; i += gridDim.x * blockDim.x) g_h[i] = 0.f;
    if (blockIdx.x == 0 && threadIdx.x < Rr) g_hn2[threadIdx.x] = 0.f;
}

// ---------------- embedding + project (warp per row) ----------------
__global__ void k_embed(const int* __restrict__ prem, const int* __restrict__ hyp,
                        const float* __restrict__ emb) {
    int warp = (blockIdx.x * blockDim.x + threadIdx.x) >> 5;
    int lane = threadIdx.x & 31;
    if (warp >= NROWS) return;
    int which = warp / (Bb * Ss);
    int idx   = warp % (Bb * Ss);
    int b = idx / Ss, s = idx % Ss;
    int tok = which ? hyp[b * Ss + s] : prem[b * Ss + s];
    const float* src = emb + (size_t)tok * Ed;
    float s2 = 0.f;
    for (int e = lane; e < Ed; e += 32) { float v = src[e]; s2 += v * v; }
    s2 = warpSum(s2);
    float n  = sqrtf(fmaxf(s2, 1e-12f));
    float sc = fminf(1.0f, 0.999f / n);
    float* dst = g_x + (size_t)warp * Ed;
    for (int e = lane; e < Ed; e += 32) dst[e] = src[e] * sc;
    if (lane == 0) g_xn2[warp] = s2 * sc * sc;
}

// ---------------- GEMM: g_ux = g_x @ U (128x128x8 tiles, TM=TN=8) ----------------
__global__ void k_gemm_ux(const float* __restrict__ Up, const float* __restrict__ Uh) {
    __shared__ float As[8][132];
    __shared__ float Bs[8][132];
    int row0 = blockIdx.x * 128, col0 = blockIdx.y * 128;
    int which = row0 / (Bb * Ss);
    const float* Bm = which ? Uh : Up;
    int tid = threadIdx.x;
    int tx = tid & 15, ty = tid >> 4;
    float acc[8][8];
    #pragma unroll
    for (int i = 0; i < 8; i++)
        #pragma unroll
        for (int j = 0; j < 8; j++) acc[i][j] = 0.f;

    int ar = tid >> 1, ak = (tid & 1) * 4;
    int bk = tid >> 5, bc = (tid & 31) * 4;

    for (int k0 = 0; k0 < Ed; k0 += 8) {
        float4 av = make_float4(0.f, 0.f, 0.f, 0.f);
        if (k0 + ak < Ed)
            av = *(const float4*)(g_x + (size_t)(row0 + ar) * Ed + k0 + ak);
        As[ak + 0][ar] = av.x; As[ak + 1][ar] = av.y;
        As[ak + 2][ar] = av.z; As[ak + 3][ar] = av.w;
        float4 bv = make_float4(0.f, 0.f, 0.f, 0.f);
        if (k0 + bk < Ed)
            bv = *(const float4*)(Bm + (size_t)(k0 + bk) * Hd + col0 + bc);
        *(float4*)&Bs[bk][bc] = bv;
        __syncthreads();
        #pragma unroll
        for (int kk = 0; kk < 8; kk++) {
            float a[8], bb[8];
            *(float4*)(a)     = *(const float4*)&As[kk][ty * 8];
            *(float4*)(a + 4) = *(const float4*)&As[kk][ty * 8 + 4];
            *(float4*)(bb)     = *(const float4*)&Bs[kk][tx * 8];
            *(float4*)(bb + 4) = *(const float4*)&Bs[kk][tx * 8 + 4];
            #pragma unroll
            for (int i = 0; i < 8; i++)
                #pragma unroll
                for (int j = 0; j < 8; j++) acc[i][j] += a[i] * bb[j];
        }
        __syncthreads();
    }
    #pragma unroll
    for (int i = 0; i < 8; i++) {
        float* dst = g_ux + (size_t)(row0 + ty * 8 + i) * Hd + col0 + tx * 8;
        *(float4*)dst       = *(float4*)&acc[i][0];
        *(float4*)(dst + 4) = *(float4*)&acc[i][4];
    }
}

// ---------------- mmatvec nonlinearity + project on g_ux (warp per row) ----------------
__global__ void k_ux_post() {
    int row  = (blockIdx.x * blockDim.x + threadIdx.x) >> 5;
    int lane = threadIdx.x & 31;
    if (row >= NROWS) return;
    float* u = g_ux + (size_t)row * Hd;
    float v[32];
    float s2 = 0.f;
    #pragma unroll
    for (int i = 0; i < 32; i++) { v[i] = u[i * 32 + lane]; s2 += v[i] * v[i]; }
    float un2 = warpSum(s2);
    float xn = sqrtf(fmaxf(g_xn2[row], 1e-12f));
    float un = sqrtf(fmaxf(un2, 1e-12f));
    float mm = tanhf(un / xn * artanh_c(xn)) / un;
    float vn2 = mm * mm * un2;
    float pn  = sqrtf(fmaxf(vn2, 1e-12f));
    float ps  = fminf(1.0f, 0.999f / pn);
    float c   = mm * ps;
    #pragma unroll
    for (int i = 0; i < 32; i++) u[i * 32 + lane] = v[i] * c;
}

// ---------------- recurrent GEMM: u_part[ks] = h @ W (64x64 tiles, k-split 4) ----------------
__global__ void k_gemm_step(int useLast, const float* __restrict__ W0,
                            const float* __restrict__ W1) {
    __shared__ float As[16][68];
    __shared__ float Bs[16][68];
    const float* Asrc = useLast ? g_last : g_h;
    int row0 = blockIdx.x * 64, col0 = blockIdx.y * 64, kbase = blockIdx.z * 256;
    const float* Wm = (row0 < Bb) ? W0 : W1;
    int tid = threadIdx.x;
    int tx = tid & 15, ty = tid >> 4;
    float acc[4][4];
    #pragma unroll
    for (int i = 0; i < 4; i++)
        #pragma unroll
        for (int j = 0; j < 4; j++) acc[i][j] = 0.f;

    int ar = tid >> 2, ak = (tid & 3) * 4;
    int bk = tid >> 4, bc = (tid & 15) * 4;

    for (int k0 = kbase; k0 < kbase + 256; k0 += 16) {
        float4 av = *(const float4*)(Asrc + (size_t)(row0 + ar) * Hd + k0 + ak);
        As[ak + 0][ar] = av.x; As[ak + 1][ar] = av.y;
        As[ak + 2][ar] = av.z; As[ak + 3][ar] = av.w;
        float4 bv = *(const float4*)(Wm + (size_t)(k0 + bk) * Hd + col0 + bc);
        *(float4*)&Bs[bk][bc] = bv;
        __syncthreads();
        #pragma unroll
        for (int kk = 0; kk < 16; kk++) {
            float a[4], bb[4];
            *(float4*)a  = *(const float4*)&As[kk][ty * 4];
            *(float4*)bb = *(const float4*)&Bs[kk][tx * 4];
            #pragma unroll
            for (int i = 0; i < 4; i++)
                #pragma unroll
                for (int j = 0; j < 4; j++) acc[i][j] += a[i] * bb[j];
        }
        __syncthreads();
    }
    float* base = g_upart + (size_t)blockIdx.z * Rr * Hd;
    #pragma unroll
    for (int i = 0; i < 4; i++)
        *(float4*)(base + (size_t)(row0 + ty * 4 + i) * Hd + col0 + tx * 4) =
            *(float4*)&acc[i][0];
}

// ---------------- per-step Mobius epilogue (CTA per row) ----------------
__global__ void k_step_post(int ts, const int* __restrict__ p_len,
                            const int* __restrict__ h_len,
                            const float* __restrict__ bp,
                            const float* __restrict__ bh) {
    __shared__ float sred[8][8];
    int r = blockIdx.x, tid = threadIdx.x;
    int which = r >> 7, b = r & 127;
    const float* bias = which ? bh : bp;
    int j0 = tid * 4;

    // sum k-split partials
    float u[4];
    {
        float4 a0 = *(const float4*)&g_upart[0 * Rr * Hd + (size_t)r * Hd + j0];
        float4 a1 = *(const float4*)&g_upart[1 * Rr * Hd + (size_t)r * Hd + j0];
        float4 a2 = *(const float4*)&g_upart[2 * Rr * Hd + (size_t)r * Hd + j0];
        float4 a3 = *(const float4*)&g_upart[3 * Rr * Hd + (size_t)r * Hd + j0];
        u[0] = a0.x + a1.x + a2.x + a3.x;
        u[1] = a0.y + a1.y + a2.y + a3.y;
        u[2] = a0.z + a1.z + a2.z + a3.z;
        u[3] = a0.w + a1.w + a2.w + a3.w;
    }
    float ux[4], bv[4];
    {
        float4 t4 = *(const float4*)&g_ux[((size_t)which * Bb * Ss + (size_t)b * Ss + ts) * Hd + j0];
        ux[0] = t4.x; ux[1] = t4.y; ux[2] = t4.z; ux[3] = t4.w;
        float4 b4 = *(const float4*)&bias[j0];
        bv[0] = b4.x; bv[1] = b4.y; bv[2] = b4.z; bv[3] = b4.w;
    }

    float red[6] = {0.f, 0.f, 0.f, 0.f, 0.f, 0.f};
    #pragma unroll
    for (int i = 0; i < 4; i++) {
        red[0] += u[i]  * u[i];
        red[1] += ux[i] * ux[i];
        red[2] += bv[i] * bv[i];
        red[3] += u[i]  * ux[i];
        red[4] += u[i]  * bv[i];
        red[5] += ux[i] * bv[i];
    }
    blockReduceN<6>(red, sred);
    float su2 = red[0], sux2 = red[1], sb2 = red[2];
    float suux = red[3], sub = red[4], suxb = red[5];

    // mmatvec(h, W) scale + project  -> v = c1 * u
    float xn = sqrtf(fmaxf(g_hn2[r], 1e-12f));
    float un = sqrtf(fmaxf(su2, 1e-12f));
    float mm = tanhf(un / xn * artanh_c(xn)) / un;
    float vn2 = mm * mm * su2;
    float pn = sqrtf(fmaxf(vn2, 1e-12f));
    float ps = fminf(1.0f, 0.999f / pn);
    float c1 = mm * ps;

    // madd(v, ux) + project -> z = A1*u + B1*ux
    float x2 = c1 * c1 * su2, y2 = sux2, xy = c1 * suux;
    float al = 1.f + 2.f * xy + y2;
    float be = 1.f - x2;
    float den = fmaxf(1.f + 2.f * xy + x2 * y2, 1e-12f);
    float zn2p = (al * al * x2 + 2.f * al * be * xy + be * be * y2) / (den * den);
    float zn = sqrtf(fmaxf(zn2p, 1e-12f));
    float zs = fminf(1.0f, 0.999f / zn);
    float c2 = zs / den;
    float A1 = c2 * al * c1, B1 = c2 * be;
    float z2 = zn2p * zs * zs;

    // madd(z, bias) + project -> w = Au*u + Aux*ux + Ab*b
    float xy2 = A1 * sub + B1 * suxb;
    float al2 = 1.f + 2.f * xy2 + sb2;
    float be2 = 1.f - z2;
    float den2 = fmaxf(1.f + 2.f * xy2 + z2 * sb2, 1e-12f);
    float wn2p = (al2 * al2 * z2 + 2.f * al2 * be2 * xy2 + be2 * be2 * sb2) / (den2 * den2);
    float wn = sqrtf(fmaxf(wn2p, 1e-12f));
    float ws = fminf(1.0f, 0.999f / wn);
    float c3 = ws / den2;
    float Au = c3 * al2 * A1, Aux = c3 * al2 * B1, Ab = c3 * be2;
    float wnf2 = wn2p * ws * ws;
    float wnf = sqrtf(fmaxf(wnf2, 1e-12f));

    // mtanh: log0 scale, elementwise tanh, reduce, exp0 + project
    float lam = artanh_c(wnf) / wnf;
    float tt[4];
    float red2[1] = {0.f};
    #pragma unroll
    for (int i = 0; i < 4; i++) {
        tt[i] = tanhf(lam * (Au * u[i] + Aux * ux[i] + Ab * bv[i]));
        red2[0] += tt[i] * tt[i];
    }
    blockReduceN<1>(red2, sred);
    float st2 = red2[0];
    float tn = sqrtf(fmaxf(st2, 1e-12f));
    float es = tanhf(tn) / tn;
    float en2 = es * es * st2;
    float enn = sqrtf(fmaxf(en2, 1e-12f));
    float epss = fminf(1.0f, 0.999f / enn);
    float c4 = es * epss;

    float4 hv;
    hv.x = c4 * tt[0]; hv.y = c4 * tt[1]; hv.z = c4 * tt[2]; hv.w = c4 * tt[3];
    *(float4*)&g_h[(size_t)r * Hd + j0] = hv;
    int lenv = which ? h_len[b] : p_len[b];
    bool save = (ts == lenv - 1);
    if (save) *(float4*)&g_last[(size_t)r * Hd + j0] = hv;
    if (tid == 0) {
        float hn2n = c4 * c4 * st2;
        g_hn2[r] = hn2n;
        if (save) g_lastn2[r] = hn2n;
    }
}

// ---------------- hlinear epilogue: g_rep = madd(mmatvec(last, Wc), bc) ----------------
__global__ void k_final_post(const float* __restrict__ bcp, const float* __restrict__ bch) {
    __shared__ float sred[8][8];
    int r = blockIdx.x, tid = threadIdx.x;
    int which = r >> 7;
    const float* bias = which ? bch : bcp;
    int j0 = tid * 4;

    float u[4];
    {
        float4 a0 = *(const float4*)&g_upart[0 * Rr * Hd + (size_t)r * Hd + j0];
        float4 a1 = *(const float4*)&g_upart[1 * Rr * Hd + (size_t)r * Hd + j0];
        float4 a2 = *(const float4*)&g_upart[2 * Rr * Hd + (size_t)r * Hd + j0];
        float4 a3 = *(const float4*)&g_upart[3 * Rr * Hd + (size_t)r * Hd + j0];
        u[0] = a0.x + a1.x + a2.x + a3.x;
        u[1] = a0.y + a1.y + a2.y + a3.y;
        u[2] = a0.z + a1.z + a2.z + a3.z;
        u[3] = a0.w + a1.w + a2.w + a3.w;
    }
    float bv[4];
    {
        float4 b4 = *(const float4*)&bias[j0];
        bv[0] = b4.x; bv[1] = b4.y; bv[2] = b4.z; bv[3] = b4.w;
    }
    float red[3] = {0.f, 0.f, 0.f};
    #pragma unroll
    for (int i = 0; i < 4; i++) {
        red[0] += u[i] * u[i];
        red[1] += bv[i] * bv[i];
        red[2] += u[i] * bv[i];
    }
    blockReduceN<3>(red, sred);
    float su2 = red[0], sb2 = red[1], sub = red[2];

    float xn = sqrtf(fmaxf(g_lastn2[r], 1e-12f));
    float un = sqrtf(fmaxf(su2, 1e-12f));
    float mm = tanhf(un / xn * artanh_c(xn)) / un;
    float vn2 = mm * mm * su2;
    float pn = sqrtf(fmaxf(vn2, 1e-12f));
    float ps = fminf(1.0f, 0.999f / pn);
    float c1 = mm * ps;

    float x2 = c1 * c1 * su2, y2 = sb2, xy = c1 * sub;
    float al = 1.f + 2.f * xy + y2;
    float be = 1.f - x2;
    float den = fmaxf(1.f + 2.f * xy + x2 * y2, 1e-12f);
    float zn2p = (al * al * x2 + 2.f * al * be * xy + be * be * y2) / (den * den);
    float zn = sqrtf(fmaxf(zn2p, 1e-12f));
    float zs = fminf(1.0f, 0.999f / zn);
    float c2 = zs / den;
    float A1 = c2 * al * c1, B1 = c2 * be;

    float4 o;
    o.x = A1 * u[0] + B1 * bv[0];
    o.y = A1 * u[1] + B1 * bv[1];
    o.z = A1 * u[2] + B1 * bv[2];
    o.w = A1 * u[3] + B1 * bv[3];
    *(float4*)&g_rep[(size_t)r * Hd + j0] = o;
}

// ---------------- rep = madd(p_rep, h_rep); MLR logits ----------------
__global__ void k_mlr(const float* __restrict__ a_mlr, const float* __restrict__ p_mlr,
                      float* __restrict__ out) {
    __shared__ float sred[8][8];
    int b = blockIdx.x, tid = threadIdx.x;
    int j0 = tid * 4;
    float x[4], y[4];
    {
        float4 x4 = *(const float4*)&g_rep[(size_t)b * Hd + j0];
        float4 y4 = *(const float4*)&g_rep[(size_t)(128 + b) * Hd + j0];
        x[0] = x4.x; x[1] = x4.y; x[2] = x4.z; x[3] = x4.w;
        y[0] = y4.x; y[1] = y4.y; y[2] = y4.z; y[3] = y4.w;
    }
    float red[3] = {0.f, 0.f, 0.f};
    #pragma unroll
    for (int i = 0; i < 4; i++) {
        red[0] += x[i] * x[i];
        red[1] += y[i] * y[i];
        red[2] += x[i] * y[i];
    }
    blockReduceN<3>(red, sred);
    float x2 = red[0], y2 = red[1], xy = red[2];
    float al = 1.f + 2.f * xy + y2;
    float be = 1.f - x2;
    float den = fmaxf(1.f + 2.f * xy + x2 * y2, 1e-12f);
    float rn2 = (al * al * x2 + 2.f * al * be * xy + be * be * y2) / (den * den);
    float rn = sqrtf(fmaxf(rn2, 1e-12f));
    float rs = fminf(1.0f, 0.999f / rn);
    float cr = rs / den;
    float rep[4];
    #pragma unroll
    for (int i = 0; i < 4; i++) rep[i] = cr * (al * x[i] + be * y[i]);
    float rep2 = rn2 * rs * rs;

    for (int k = 0; k < NCc; k++) {
        float p[4], a[4];
        {
            float4 p4 = *(const float4*)&p_mlr[(size_t)k * Hd + j0];
            float4 a4 = *(const float4*)&a_mlr[(size_t)k * Hd + j0];
            p[0] = p4.x; p[1] = p4.y; p[2] = p4.z; p[3] = p4.w;
            a[0] = a4.x; a[1] = a4.y; a[2] = a4.z; a[3] = a4.w;
        }
        float r5[5] = {0.f, 0.f, 0.f, 0.f, 0.f};
        #pragma unroll
        for (int i = 0; i < 4; i++) {
            r5[0] += p[i] * p[i];        // sp2
            r5[1] += a[i] * a[i];        // sa2
            r5[2] += rep[i] * p[i];      // spr
            r5[3] += p[i] * a[i];        // spa
            r5[4] += rep[i] * a[i];      // sar
        }
        blockReduceN<5>(r5, sred);
        float sp2 = r5[0], sa2 = r5[1], spr = r5[2], spa = r5[3], sar = r5[4];

        // madd(-p, rep): x = -p, y = rep
        float xym = -spr;
        float alm = 1.f + 2.f * xym + rep2;
        float bem = 1.f - sp2;
        float denm = fmaxf(1.f + 2.f * xym + sp2 * rep2, 1e-12f);
        float zn2 = (alm * alm * sp2 + 2.f * alm * bem * xym + bem * bem * rep2) / (denm * denm);
        float znn = sqrtf(fmaxf(zn2, 1e-12f));
        float zss = fminf(1.0f, 0.999f / znn);
        float cz = zss / denm;
        float z2 = zn2 * zss * zss;
        float za = cz * (alm * (-spa) + bem * sar);
        float an = sqrtf(fmaxf(sa2, 1e-12f));
        float lamk = 2.0f / fmaxf(1.0f - sp2, 1e-5f);
        float logit = lamk * an * asinhf(2.0f * za / (fmaxf(1.0f - z2, 1e-5f) * an));
        if (tid == 0) out[b * NCc + k] = logit;
        __syncthreads();
    }
}

// ---------------- launch ----------------
extern "C" void kernel_launch(void* const* d_in, const int* in_sizes, int n_in,
                              void* d_out, int out_size) {
    const int*   prem   = (const int*)  d_in[0];
    const int*   p_len  = (const int*)  d_in[1];
    const int*   hyp    = (const int*)  d_in[2];
    const int*   h_len  = (const int*)  d_in[3];
    const float* emb    = (const float*)d_in[4];
    const float* Wp     = (const float*)d_in[5];
    const float* Up     = (const float*)d_in[6];
    const float* bp     = (const float*)d_in[7];
    const float* Wh     = (const float*)d_in[8];
    const float* Uh     = (const float*)d_in[9];
    const float* bh     = (const float*)d_in[10];
    const float* Wcp    = (const float*)d_in[11];
    const float* bcp    = (const float*)d_in[12];
    const float* Wch    = (const float*)d_in[13];
    const float* bch    = (const float*)d_in[14];
    const float* a_mlr  = (const float*)d_in[15];
    const float* p_mlr  = (const float*)d_in[16];
    float* out = (float*)d_out;

    k_init<<<128, 256>>>();
    k_embed<<<NROWS / 8, 256>>>(prem, hyp, emb);
    {
        dim3 g(NROWS / 128, Hd / 128);
        k_gemm_ux<<<g, 256>>>(Up, Uh);
    }
    k_ux_post<<<NROWS / 8, 256>>>();

    dim3 gstep(4, 16, 4);
    for (int t = 0; t < Ss; t++) {
        k_gemm_step<<<gstep, 256>>>(0, Wp, Wh);
        k_step_post<<<Rr, 256>>>(t, p_len, h_len, bp, bh);
    }
    k_gemm_step<<<gstep, 256>>>(1, Wcp, Wch);
    k_final_post<<<Rr, 256>>>(bcp, bch);
    k_mlr<<<Bb, 256>>>(a_mlr, p_mlr, out);
}

// round 5
// speedup vs baseline: 1.1147x; 1.0768x over previous
#include <cuda_runtime.h>
#include <math.h>

#define Bb   128
#define Ss   256
#define Ed   300
#define Hd   1024
#define NCc  3
#define Rr   256                 // 2*Bb rows (premise rows 0..127, hypothesis 128..255)
#define NROWS (2*Bb*Ss)          // 65536 flattened (which, b, s) rows
#define GRID_LOOP 128

// ---------------- device scratch (static, allocation-free) ----------------
__device__ float g_x   [(size_t)NROWS * Ed];   // projected embeddings
__device__ float g_xn2 [NROWS];                // ||x||^2 post-project
__device__ float g_ux  [(size_t)NROWS * Hd];   // mmatvec(x_t, U) results
__device__ float g_h   [Rr * Hd];              // current hidden states (both RNNs)
__device__ float g_hn2 [Rr];
__device__ float g_part[(size_t)8 * Rr * Hd];  // 8-way k-split partials (persistent loop)
__device__ float g_upart[4 * Rr * Hd];         // k-split partials (final hlinear GEMM)
__device__ float g_last[Rr * Hd];              // h at t = len-1
__device__ float g_lastn2[Rr];
__device__ float g_rep [Rr * Hd];              // hlinear outputs
__device__ unsigned g_barrier;                 // monotonic grid barrier counter

// ---------------- helpers ----------------
__device__ __forceinline__ float warpSum(float v) {
    #pragma unroll
    for (int o = 16; o; o >>= 1) v += __shfl_xor_sync(0xffffffffu, v, o);
    return v;
}

// block = 256 threads (8 warps). Reduces NV values; result broadcast to all threads.
template<int NV>
__device__ __forceinline__ void blockReduceN(float (&vals)[NV], float (*sred)[8]) {
    int tid = threadIdx.x, lane = tid & 31, w = tid >> 5;
    #pragma unroll
    for (int i = 0; i < NV; i++) {
        float v = warpSum(vals[i]);
        if (lane == 0) sred[i][w] = v;
    }
    __syncthreads();
    #pragma unroll
    for (int i = 0; i < NV; i++) {
        float t = 0.f;
        #pragma unroll
        for (int k = 0; k < 8; k++) t += sred[i][k];
        vals[i] = t;
    }
    __syncthreads();
}

// grouped reduce: warps 0-3 = group 0, warps 4-7 = group 1 (two independent rows)
template<int NV>
__device__ __forceinline__ void groupReduceN(float (&vals)[NV], float (*sred)[8], int grp) {
    int tid = threadIdx.x, lane = tid & 31, w = tid >> 5;
    #pragma unroll
    for (int i = 0; i < NV; i++) {
        float v = warpSum(vals[i]);
        if (lane == 0) sred[i][w] = v;
    }
    __syncthreads();
    #pragma unroll
    for (int i = 0; i < NV; i++) {
        int b = grp * 4;
        vals[i] = sred[i][b] + sred[i][b + 1] + sred[i][b + 2] + sred[i][b + 3];
    }
    __syncthreads();
}

__device__ __forceinline__ float artanh_c(float x) {
    return atanhf(fminf(x, 0.99999f));
}

// packed fp32x2 FMA (full-rate fp32 on Blackwell)
__device__ __forceinline__ void fma2(unsigned long long &acc, unsigned long long a,
                                     unsigned long long b) {
    asm("fma.rn.f32x2 %0, %1, %2, %0;" : "+l"(acc) : "l"(a), "l"(b));
}
__device__ __forceinline__ unsigned long long dup2(float s) {
    unsigned long long d;
    asm("mov.b64 %0, {%1, %1};" : "=l"(d) : "f"(s));
    return d;
}

// grid barrier: monotonic counter, release-arrive / acquire-spin
__device__ __forceinline__ void gridSync(unsigned &target) {
    __syncthreads();
    if (threadIdx.x == 0) {
        __threadfence();
        unsigned old;
        asm volatile("atom.release.gpu.add.u32 %0, [%1], %2;"
                     : "=r"(old) : "l"(&g_barrier), "r"(1u) : "memory");
        unsigned cur = old + 1;
        while (cur < target) {
            asm volatile("ld.acquire.gpu.u32 %0, [%1];"
                         : "=r"(cur) : "l"(&g_barrier) : "memory");
        }
    }
    __syncthreads();
    target += GRID_LOOP;
}

// ---------------- init ----------------
__global__ void k_init() {
    int i = blockIdx.x * blockDim.x + threadIdx.x;
    int n = Rr * Hd;
    for (; i < n; i += gridDim.x * blockDim.x) g_h[i] = 0.f;
    if (blockIdx.x == 0 && threadIdx.x < Rr) g_hn2[threadIdx.x] = 0.f;
    if (blockIdx.x == 0 && threadIdx.x == 0) g_barrier = 0u;
}

// ---------------- embedding + project (warp per row) ----------------
__global__ void k_embed(const int* __restrict__ prem, const int* __restrict__ hyp,
                        const float* __restrict__ emb) {
    int warp = (blockIdx.x * blockDim.x + threadIdx.x) >> 5;
    int lane = threadIdx.x & 31;
    if (warp >= NROWS) return;
    int which = warp / (Bb * Ss);
    int idx   = warp % (Bb * Ss);
    int b = idx / Ss, s = idx % Ss;
    int tok = which ? hyp[b * Ss + s] : prem[b * Ss + s];
    const float* src = emb + (size_t)tok * Ed;
    float s2 = 0.f;
    for (int e = lane; e < Ed; e += 32) { float v = src[e]; s2 += v * v; }
    s2 = warpSum(s2);
    float n  = sqrtf(fmaxf(s2, 1e-12f));
    float sc = fminf(1.0f, 0.999f / n);
    float* dst = g_x + (size_t)warp * Ed;
    for (int e = lane; e < Ed; e += 32) dst[e] = src[e] * sc;
    if (lane == 0) g_xn2[warp] = s2 * sc * sc;
}

// ---------------- GEMM: g_ux = g_x @ U (128x128x8 tiles, f32x2) ----------------
__global__ void k_gemm_ux(const float* __restrict__ Up, const float* __restrict__ Uh) {
    __shared__ __align__(16) float As[8][132];
    __shared__ __align__(16) float Bs[8][132];
    int row0 = blockIdx.x * 128, col0 = blockIdx.y * 128;
    int which = row0 / (Bb * Ss);
    const float* Bm = which ? Uh : Up;
    int tid = threadIdx.x;
    int tx = tid & 15, ty = tid >> 4;
    __align__(16) unsigned long long acc[8][4];
    #pragma unroll
    for (int i = 0; i < 8; i++)
        #pragma unroll
        for (int j = 0; j < 4; j++) acc[i][j] = 0ull;

    int ar = tid >> 1, ak = (tid & 1) * 4;
    int bk = tid >> 5, bc = (tid & 31) * 4;

    for (int k0 = 0; k0 < Ed; k0 += 8) {
        float4 av = make_float4(0.f, 0.f, 0.f, 0.f);
        if (k0 + ak < Ed)
            av = *(const float4*)(g_x + (size_t)(row0 + ar) * Ed + k0 + ak);
        As[ak + 0][ar] = av.x; As[ak + 1][ar] = av.y;
        As[ak + 2][ar] = av.z; As[ak + 3][ar] = av.w;
        float4 bv = make_float4(0.f, 0.f, 0.f, 0.f);
        if (k0 + bk < Ed)
            bv = *(const float4*)(Bm + (size_t)(k0 + bk) * Hd + col0 + bc);
        *(float4*)&Bs[bk][bc] = bv;
        __syncthreads();
        #pragma unroll
        for (int kk = 0; kk < 8; kk++) {
            float a[8];
            *(float4*)(a)     = *(const float4*)&As[kk][ty * 8];
            *(float4*)(a + 4) = *(const float4*)&As[kk][ty * 8 + 4];
            const unsigned long long* bsp = (const unsigned long long*)&Bs[kk][tx * 8];
            unsigned long long bP0 = bsp[0], bP1 = bsp[1], bP2 = bsp[2], bP3 = bsp[3];
            #pragma unroll
            for (int i = 0; i < 8; i++) {
                unsigned long long aD = dup2(a[i]);
                fma2(acc[i][0], aD, bP0);
                fma2(acc[i][1], aD, bP1);
                fma2(acc[i][2], aD, bP2);
                fma2(acc[i][3], aD, bP3);
            }
        }
        __syncthreads();
    }
    #pragma unroll
    for (int i = 0; i < 8; i++) {
        float* dst = g_ux + (size_t)(row0 + ty * 8 + i) * Hd + col0 + tx * 8;
        *(float4*)dst       = *(float4*)&acc[i][0];
        *(float4*)(dst + 4) = *(float4*)&acc[i][2];
    }
}

// ---------------- mmatvec nonlinearity + project on g_ux (warp per row) ----------------
__global__ void k_ux_post() {
    int row  = (blockIdx.x * blockDim.x + threadIdx.x) >> 5;
    int lane = threadIdx.x & 31;
    if (row >= NROWS) return;
    float* u = g_ux + (size_t)row * Hd;
    float v[32];
    float s2 = 0.f;
    #pragma unroll
    for (int i = 0; i < 32; i++) { v[i] = u[i * 32 + lane]; s2 += v[i] * v[i]; }
    float un2 = warpSum(s2);
    float xn = sqrtf(fmaxf(g_xn2[row], 1e-12f));
    float un = sqrtf(fmaxf(un2, 1e-12f));
    float mm = tanhf(un / xn * artanh_c(xn)) / un;
    float vn2 = mm * mm * un2;
    float pn  = sqrtf(fmaxf(vn2, 1e-12f));
    float ps  = fminf(1.0f, 0.999f / pn);
    float c   = mm * ps;
    #pragma unroll
    for (int i = 0; i < 32; i++) u[i * 32 + lane] = v[i] * c;
}

// ---------------- persistent recurrence: 256 steps, 2 grid syncs per step ----------------
__global__ void __launch_bounds__(256, 1) k_loop(
    const int* __restrict__ p_len, const int* __restrict__ h_len,
    const float* __restrict__ bp, const float* __restrict__ bh,
    const float* __restrict__ Wp, const float* __restrict__ Wh)
{
    __shared__ __align__(16) float As[8][132];
    __shared__ __align__(16) float Bs[8][132];
    __shared__ float sred[8][8];

    const int tid = threadIdx.x;
    const int bid = blockIdx.x;

    // phase A decode: 16 tiles (2 row-tiles x 8 col-tiles) x 8 k-splits
    const int ksA  = bid & 7;
    const int tile = bid >> 3;
    const int rt = tile >> 3, ct = tile & 7;
    const int row0 = rt * 128, col0 = ct * 128, kb = ksA * 128;
    const float* WmA = rt ? Wh : Wp;
    const int tx = tid & 15, ty = tid >> 4;
    const int ar = tid >> 1, ak = (tid & 1) * 4;
    const int bk = tid >> 5, bc = (tid & 31) * 4;

    // phase B decode: CTA owns rows 2*bid, 2*bid+1; half-block per row
    const int half = tid >> 7;
    const int t8 = tid & 127;
    const int j0 = t8 * 8;
    const int rB = bid * 2 + half;
    const int whichB = rB >> 7, bBB = rB & 127;
    const float* biasB = whichB ? bh : bp;
    const int lenB = whichB ? h_len[bBB] : p_len[bBB];
    float bv[8];
    #pragma unroll
    for (int i = 0; i < 8; i++) bv[i] = biasB[j0 + i];
    float hn2 = 0.f;                      // ||h||^2, carried in registers
    unsigned target = GRID_LOOP;

    for (int t = 0; t < Ss; t++) {
        // ===== phase A: partial GEMM v_part = h @ W over K chunk =====
        __align__(16) unsigned long long acc[8][4];
        #pragma unroll
        for (int i = 0; i < 8; i++)
            #pragma unroll
            for (int j = 0; j < 4; j++) acc[i][j] = 0ull;

        float4 avS = __ldcg((const float4*)(g_h + (size_t)(row0 + ar) * Hd + kb + ak));
        float4 bvS = *(const float4*)(WmA + (size_t)(kb + bk) * Hd + col0 + bc);

        for (int k0 = kb; k0 < kb + 128; k0 += 8) {
            __syncthreads();
            As[ak + 0][ar] = avS.x; As[ak + 1][ar] = avS.y;
            As[ak + 2][ar] = avS.z; As[ak + 3][ar] = avS.w;
            *(float4*)&Bs[bk][bc] = bvS;
            __syncthreads();
            if (k0 + 8 < kb + 128) {
                avS = __ldcg((const float4*)(g_h + (size_t)(row0 + ar) * Hd + k0 + 8 + ak));
                bvS = *(const float4*)(WmA + (size_t)(k0 + 8 + bk) * Hd + col0 + bc);
            }
            #pragma unroll
            for (int kk = 0; kk < 8; kk++) {
                float a[8];
                *(float4*)(a)     = *(const float4*)&As[kk][ty * 8];
                *(float4*)(a + 4) = *(const float4*)&As[kk][ty * 8 + 4];
                const unsigned long long* bsp = (const unsigned long long*)&Bs[kk][tx * 8];
                unsigned long long bP0 = bsp[0], bP1 = bsp[1], bP2 = bsp[2], bP3 = bsp[3];
                #pragma unroll
                for (int i = 0; i < 8; i++) {
                    unsigned long long aD = dup2(a[i]);
                    fma2(acc[i][0], aD, bP0);
                    fma2(acc[i][1], aD, bP1);
                    fma2(acc[i][2], aD, bP2);
                    fma2(acc[i][3], aD, bP3);
                }
            }
        }
        {
            float* pb = g_part + ((size_t)ksA * Rr + row0) * Hd + col0;
            #pragma unroll
            for (int i = 0; i < 8; i++) {
                float* dst = pb + (size_t)(ty * 8 + i) * Hd + tx * 8;
                __stcg((float4*)dst,       *(float4*)&acc[i][0]);
                __stcg((float4*)(dst + 4), *(float4*)&acc[i][2]);
            }
        }
        gridSync(target);

        // ===== phase B: reduce partials + Mobius epilogue (row-local) =====
        float u[8];
        #pragma unroll
        for (int i = 0; i < 8; i++) u[i] = 0.f;
        #pragma unroll
        for (int s = 0; s < 8; s++) {
            const float4* p = (const float4*)(g_part + ((size_t)s * Rr + rB) * Hd + j0);
            float4 q0 = __ldcg(p), q1 = __ldcg(p + 1);
            u[0] += q0.x; u[1] += q0.y; u[2] += q0.z; u[3] += q0.w;
            u[4] += q1.x; u[5] += q1.y; u[6] += q1.z; u[7] += q1.w;
        }
        float ux[8];
        {
            const float4* p = (const float4*)(g_ux +
                ((size_t)whichB * Bb * Ss + (size_t)bBB * Ss + t) * Hd + j0);
            float4 q0 = p[0], q1 = p[1];
            ux[0] = q0.x; ux[1] = q0.y; ux[2] = q0.z; ux[3] = q0.w;
            ux[4] = q1.x; ux[5] = q1.y; ux[6] = q1.z; ux[7] = q1.w;
        }

        float red[6] = {0.f, 0.f, 0.f, 0.f, 0.f, 0.f};
        #pragma unroll
        for (int i = 0; i < 8; i++) {
            red[0] += u[i]  * u[i];
            red[1] += ux[i] * ux[i];
            red[2] += bv[i] * bv[i];
            red[3] += u[i]  * ux[i];
            red[4] += u[i]  * bv[i];
            red[5] += ux[i] * bv[i];
        }
        groupReduceN<6>(red, sred, half);
        float su2 = red[0], sux2 = red[1], sb2 = red[2];
        float suux = red[3], sub = red[4], suxb = red[5];

        // mmatvec(h, W) scale + project  -> v = c1 * u
        float xn = sqrtf(fmaxf(hn2, 1e-12f));
        float un = sqrtf(fmaxf(su2, 1e-12f));
        float mm = tanhf(un / xn * artanh_c(xn)) / un;
        float vn2 = mm * mm * su2;
        float pn = sqrtf(fmaxf(vn2, 1e-12f));
        float ps = fminf(1.0f, 0.999f / pn);
        float c1 = mm * ps;

        // madd(v, ux) + project -> z = A1*u + B1*ux
        float x2 = c1 * c1 * su2, y2 = sux2, xy = c1 * suux;
        float al = 1.f + 2.f * xy + y2;
        float be = 1.f - x2;
        float den = fmaxf(1.f + 2.f * xy + x2 * y2, 1e-12f);
        float zn2p = (al * al * x2 + 2.f * al * be * xy + be * be * y2) / (den * den);
        float zn = sqrtf(fmaxf(zn2p, 1e-12f));
        float zs = fminf(1.0f, 0.999f / zn);
        float c2 = zs / den;
        float A1 = c2 * al * c1, B1 = c2 * be;
        float z2 = zn2p * zs * zs;

        // madd(z, bias) + project -> w = Au*u + Aux*ux + Ab*b
        float xy2 = A1 * sub + B1 * suxb;
        float al2 = 1.f + 2.f * xy2 + sb2;
        float be2 = 1.f - z2;
        float den2 = fmaxf(1.f + 2.f * xy2 + z2 * sb2, 1e-12f);
        float wn2p = (al2 * al2 * z2 + 2.f * al2 * be2 * xy2 + be2 * be2 * sb2) / (den2 * den2);
        float wn = sqrtf(fmaxf(wn2p, 1e-12f));
        float ws = fminf(1.0f, 0.999f / wn);
        float c3 = ws / den2;
        float Au = c3 * al2 * A1, Aux = c3 * al2 * B1, Ab = c3 * be2;
        float wnf2 = wn2p * ws * ws;
        float wnf = sqrtf(fmaxf(wnf2, 1e-12f));

        // mtanh
        float lam = artanh_c(wnf) / wnf;
        float tt[8];
        float red2[1] = {0.f};
        #pragma unroll
        for (int i = 0; i < 8; i++) {
            tt[i] = tanhf(lam * (Au * u[i] + Aux * ux[i] + Ab * bv[i]));
            red2[0] += tt[i] * tt[i];
        }
        groupReduceN<1>(red2, sred, half);
        float st2 = red2[0];
        float tn = sqrtf(fmaxf(st2, 1e-12f));
        float es = tanhf(tn) / tn;
        float en2 = es * es * st2;
        float enn = sqrtf(fmaxf(en2, 1e-12f));
        float epss = fminf(1.0f, 0.999f / enn);
        float c4 = es * epss;
        hn2 = c4 * c4 * st2;

        float4 h0 = make_float4(c4 * tt[0], c4 * tt[1], c4 * tt[2], c4 * tt[3]);
        float4 h1 = make_float4(c4 * tt[4], c4 * tt[5], c4 * tt[6], c4 * tt[7]);
        float* hp = g_h + (size_t)rB * Hd + j0;
        __stcg((float4*)hp,     h0);
        __stcg((float4*)hp + 1, h1);
        if (t == lenB - 1) {
            float* lp = g_last + (size_t)rB * Hd + j0;
            __stcg((float4*)lp,     h0);
            __stcg((float4*)lp + 1, h1);
            if (t8 == 0) g_lastn2[rB] = hn2;
        }
        gridSync(target);
    }
}

// ---------------- final hlinear GEMM: u_part[ks] = last @ Wc (64x64 tiles, k-split 4) ----------------
__global__ void k_gemm_step(int useLast, const float* __restrict__ W0,
                            const float* __restrict__ W1) {
    __shared__ float As[16][68];
    __shared__ float Bs[16][68];
    const float* Asrc = useLast ? g_last : g_h;
    int row0 = blockIdx.x * 64, col0 = blockIdx.y * 64, kbase = blockIdx.z * 256;
    const float* Wm = (row0 < Bb) ? W0 : W1;
    int tid = threadIdx.x;
    int tx = tid & 15, ty = tid >> 4;
    float acc[4][4];
    #pragma unroll
    for (int i = 0; i < 4; i++)
        #pragma unroll
        for (int j = 0; j < 4; j++) acc[i][j] = 0.f;

    int ar = tid >> 2, ak = (tid & 3) * 4;
    int bk = tid >> 4, bc = (tid & 15) * 4;

    for (int k0 = kbase; k0 < kbase + 256; k0 += 16) {
        float4 av = *(const float4*)(Asrc + (size_t)(row0 + ar) * Hd + k0 + ak);
        As[ak + 0][ar] = av.x; As[ak + 1][ar] = av.y;
        As[ak + 2][ar] = av.z; As[ak + 3][ar] = av.w;
        float4 bvv = *(const float4*)(Wm + (size_t)(k0 + bk) * Hd + col0 + bc);
        *(float4*)&Bs[bk][bc] = bvv;
        __syncthreads();
        #pragma unroll
        for (int kk = 0; kk < 16; kk++) {
            float a[4], bb[4];
            *(float4*)a  = *(const float4*)&As[kk][ty * 4];
            *(float4*)bb = *(const float4*)&Bs[kk][tx * 4];
            #pragma unroll
            for (int i = 0; i < 4; i++)
                #pragma unroll
                for (int j = 0; j < 4; j++) acc[i][j] += a[i] * bb[j];
        }
        __syncthreads();
    }
    float* base = g_upart + (size_t)blockIdx.z * Rr * Hd;
    #pragma unroll
    for (int i = 0; i < 4; i++)
        *(float4*)(base + (size_t)(row0 + ty * 4 + i) * Hd + col0 + tx * 4) =
            *(float4*)&acc[i][0];
}

// ---------------- hlinear epilogue: g_rep = madd(mmatvec(last, Wc), bc) ----------------
__global__ void k_final_post(const float* __restrict__ bcp, const float* __restrict__ bch) {
    __shared__ float sred[8][8];
    int r = blockIdx.x, tid = threadIdx.x;
    int which = r >> 7;
    const float* bias = which ? bch : bcp;
    int j0 = tid * 4;

    float u[4];
    {
        float4 a0 = *(const float4*)&g_upart[0 * Rr * Hd + (size_t)r * Hd + j0];
        float4 a1 = *(const float4*)&g_upart[1 * Rr * Hd + (size_t)r * Hd + j0];
        float4 a2 = *(const float4*)&g_upart[2 * Rr * Hd + (size_t)r * Hd + j0];
        float4 a3 = *(const float4*)&g_upart[3 * Rr * Hd + (size_t)r * Hd + j0];
        u[0] = a0.x + a1.x + a2.x + a3.x;
        u[1] = a0.y + a1.y + a2.y + a3.y;
        u[2] = a0.z + a1.z + a2.z + a3.z;
        u[3] = a0.w + a1.w + a2.w + a3.w;
    }
    float bv[4];
    {
        float4 b4 = *(const float4*)&bias[j0];
        bv[0] = b4.x; bv[1] = b4.y; bv[2] = b4.z; bv[3] = b4.w;
    }
    float red[3] = {0.f, 0.f, 0.f};
    #pragma unroll
    for (int i = 0; i < 4; i++) {
        red[0] += u[i] * u[i];
        red[1] += bv[i] * bv[i];
        red[2] += u[i] * bv[i];
    }
    blockReduceN<3>(red, sred);
    float su2 = red[0], sb2 = red[1], sub = red[2];

    float xn = sqrtf(fmaxf(g_lastn2[r], 1e-12f));
    float un = sqrtf(fmaxf(su2, 1e-12f));
    float mm = tanhf(un / xn * artanh_c(xn)) / un;
    float vn2 = mm * mm * su2;
    float pn = sqrtf(fmaxf(vn2, 1e-12f));
    float ps = fminf(1.0f, 0.999f / pn);
    float c1 = mm * ps;

    float x2 = c1 * c1 * su2, y2 = sb2, xy = c1 * sub;
    float al = 1.f + 2.f * xy + y2;
    float be = 1.f - x2;
    float den = fmaxf(1.f + 2.f * xy + x2 * y2, 1e-12f);
    float zn2p = (al * al * x2 + 2.f * al * be * xy + be * be * y2) / (den * den);
    float zn = sqrtf(fmaxf(zn2p, 1e-12f));
    float zs = fminf(1.0f, 0.999f / zn);
    float c2 = zs / den;
    float A1 = c2 * al * c1, B1 = c2 * be;

    float4 o;
    o.x = A1 * u[0] + B1 * bv[0];
    o.y = A1 * u[1] + B1 * bv[1];
    o.z = A1 * u[2] + B1 * bv[2];
    o.w = A1 * u[3] + B1 * bv[3];
    *(float4*)&g_rep[(size_t)r * Hd + j0] = o;
}

// ---------------- rep = madd(p_rep, h_rep); MLR logits ----------------
__global__ void k_mlr(const float* __restrict__ a_mlr, const float* __restrict__ p_mlr,
                      float* __restrict__ out) {
    __shared__ float sred[8][8];
    int b = blockIdx.x, tid = threadIdx.x;
    int j0 = tid * 4;
    float x[4], y[4];
    {
        float4 x4 = *(const float4*)&g_rep[(size_t)b * Hd + j0];
        float4 y4 = *(const float4*)&g_rep[(size_t)(128 + b) * Hd + j0];
        x[0] = x4.x; x[1] = x4.y; x[2] = x4.z; x[3] = x4.w;
        y[0] = y4.x; y[1] = y4.y; y[2] = y4.z; y[3] = y4.w;
    }
    float red[3] = {0.f, 0.f, 0.f};
    #pragma unroll
    for (int i = 0; i < 4; i++) {
        red[0] += x[i] * x[i];
        red[1] += y[i] * y[i];
        red[2] += x[i] * y[i];
    }
    blockReduceN<3>(red, sred);
    float x2 = red[0], y2 = red[1], xy = red[2];
    float al = 1.f + 2.f * xy + y2;
    float be = 1.f - x2;
    float den = fmaxf(1.f + 2.f * xy + x2 * y2, 1e-12f);
    float rn2 = (al * al * x2 + 2.f * al * be * xy + be * be * y2) / (den * den);
    float rn = sqrtf(fmaxf(rn2, 1e-12f));
    float rs = fminf(1.0f, 0.999f / rn);
    float cr = rs / den;
    float rep[4];
    #pragma unroll
    for (int i = 0; i < 4; i++) rep[i] = cr * (al * x[i] + be * y[i]);
    float rep2 = rn2 * rs * rs;

    for (int k = 0; k < NCc; k++) {
        float p[4], a[4];
        {
            float4 p4 = *(const float4*)&p_mlr[(size_t)k * Hd + j0];
            float4 a4 = *(const float4*)&a_mlr[(size_t)k * Hd + j0];
            p[0] = p4.x; p[1] = p4.y; p[2] = p4.z; p[3] = p4.w;
            a[0] = a4.x; a[1] = a4.y; a[2] = a4.z; a[3] = a4.w;
        }
        float r5[5] = {0.f, 0.f, 0.f, 0.f, 0.f};
        #pragma unroll
        for (int i = 0; i < 4; i++) {
            r5[0] += p[i] * p[i];
            r5[1] += a[i] * a[i];
            r5[2] += rep[i] * p[i];
            r5[3] += p[i] * a[i];
            r5[4] += rep[i] * a[i];
        }
        blockReduceN<5>(r5, sred);
        float sp2 = r5[0], sa2 = r5[1], spr = r5[2], spa = r5[3], sar = r5[4];

        float xym = -spr;
        float alm = 1.f + 2.f * xym + rep2;
        float bem = 1.f - sp2;
        float denm = fmaxf(1.f + 2.f * xym + sp2 * rep2, 1e-12f);
        float zn2 = (alm * alm * sp2 + 2.f * alm * bem * xym + bem * bem * rep2) / (denm * denm);
        float znn = sqrtf(fmaxf(zn2, 1e-12f));
        float zss = fminf(1.0f, 0.999f / znn);
        float cz = zss / denm;
        float z2 = zn2 * zss * zss;
        float za = cz * (alm * (-spa) + bem * sar);
        float an = sqrtf(fmaxf(sa2, 1e-12f));
        float lamk = 2.0f / fmaxf(1.0f - sp2, 1e-5f);
        float logit = lamk * an * asinhf(2.0f * za / (fmaxf(1.0f - z2, 1e-5f) * an));
        if (tid == 0) out[b * NCc + k] = logit;
        __syncthreads();
    }
}

// ---------------- launch ----------------
extern "C" void kernel_launch(void* const* d_in, const int* in_sizes, int n_in,
                              void* d_out, int out_size) {
    const int*   prem   = (const int*)  d_in[0];
    const int*   p_len  = (const int*)  d_in[1];
    const int*   hyp    = (const int*)  d_in[2];
    const int*   h_len  = (const int*)  d_in[3];
    const float* emb    = (const float*)d_in[4];
    const float* Wp     = (const float*)d_in[5];
    const float* Up     = (const float*)d_in[6];
    const float* bp     = (const float*)d_in[7];
    const float* Wh     = (const float*)d_in[8];
    const float* Uh     = (const float*)d_in[9];
    const float* bh     = (const float*)d_in[10];
    const float* Wcp    = (const float*)d_in[11];
    const float* bcp    = (const float*)d_in[12];
    const float* Wch    = (const float*)d_in[13];
    const float* bch    = (const float*)d_in[14];
    const float* a_mlr  = (const float*)d_in[15];
    const float* p_mlr  = (const float*)d_in[16];
    float* out = (float*)d_out;

    k_init<<<128, 256>>>();
    k_embed<<<NROWS / 8, 256>>>(prem, hyp, emb);
    {
        dim3 g(NROWS / 128, Hd / 128);
        k_gemm_ux<<<g, 256>>>(Up, Uh);
    }
    k_ux_post<<<NROWS / 8, 256>>>();

    k_loop<<<GRID_LOOP, 256>>>(p_len, h_len, bp, bh, Wp, Wh);

    dim3 gstep(4, 16, 4);
    k_gemm_step<<<gstep, 256>>>(1, Wcp, Wch);
    k_final_post<<<Rr, 256>>>(bcp, bch);
    k_mlr<<<Bb, 256>>>(a_mlr, p_mlr, out);
}